// round 2
// baseline (speedup 1.0000x reference)
#include <cuda_runtime.h>
#include <cuda_bf16.h>

// Problem constants (fixed by setup_inputs):
//   patches: [B=2, N=49, C=8, P=256, P=256] fp32
//   locations: 7x7 grid, origins at multiples of 128 (stride 128, patch 256)
//   output: [B, C, H=1024, W=1024] fp32
//
// Formulation: inverse gather. Output pixel (h,w) is covered by tile rows
// {h>>7 - 1, h>>7} clamped to [0,6] (ditto columns). count in {1,2,4}.
// out = sum(covering patch pixels) / (count + 1e-8), matching reference.

namespace {
constexpr int NB = 2;
constexpr int NN = 49;
constexpr int NC = 8;
constexpr int PP = 256;
constexpr int HH = 1024;
constexpr int WW = 1024;
constexpr int TILES = 7;      // 7x7 tile grid
constexpr int STRIDE = 128;

// total output float4s: B*C*H*W/4 = 4,194,304
constexpr int TOTAL_F4 = NB * NC * HH * WW / 4;
}

__global__ __launch_bounds__(256) void patch_merge_gather(
    const float* __restrict__ patches, float* __restrict__ out)
{
    int idx = blockIdx.x * blockDim.x + threadIdx.x;   // float4 index
    if (idx >= TOTAL_F4) return;

    int w4 = idx & (WW / 4 - 1);   // 0..255
    int t  = idx >> 8;
    int h  = t & (HH - 1);         // 0..1023
    int bc = t >> 10;              // b*C + c, 0..15
    int w  = w4 << 2;

    // Covering tile ranges (coverage constant over any aligned 4-wide group,
    // since all boundaries are multiples of 128).
    int thh = h >> 7;
    int t0h = thh - 1 < 0 ? 0 : thh - 1;
    int t1h = thh > TILES - 1 ? TILES - 1 : thh;
    int tww = w >> 7;
    int t0w = tww - 1 < 0 ? 0 : tww - 1;
    int t1w = tww > TILES - 1 ? TILES - 1 : tww;

    int b = bc >> 3;
    int c = bc & 7;

    float4 acc = make_float4(0.f, 0.f, 0.f, 0.f);
    int cnt = 0;

    #pragma unroll 2
    for (int th = t0h; th <= t1h; ++th) {
        int ph = h - th * STRIDE;   // 0..255
        #pragma unroll 2
        for (int tw = t0w; tw <= t1w; ++tw) {
            int pw = w - tw * STRIDE;  // 0..255, multiple of 4
            int n  = th * TILES + tw;
            // element offset in patches [B,N,C,P,P]; max < 2^26 so int is safe
            int off = (((b * NN + n) * NC + c) * (PP * PP) + ph * PP + pw) >> 2;
            float4 v = __ldg(reinterpret_cast<const float4*>(patches) + off);
            acc.x += v.x; acc.y += v.y; acc.z += v.z; acc.w += v.w;
            ++cnt;
        }
    }

    float inv = 1.0f / ((float)cnt + 1e-8f);
    acc.x *= inv; acc.y *= inv; acc.z *= inv; acc.w *= inv;
    reinterpret_cast<float4*>(out)[idx] = acc;
}

extern "C" void kernel_launch(void* const* d_in, const int* in_sizes, int n_in,
                              void* d_out, int out_size)
{
    const float* patches = (const float*)d_in[0];
    float* out = (float*)d_out;
    dim3 block(256);
    dim3 grid((TOTAL_F4 + 255) / 256);
    patch_merge_gather<<<grid, block>>>(patches, out);
}

// round 5
// speedup vs baseline: 1.0901x; 1.0901x over previous
#include <cuda_runtime.h>
#include <cuda_bf16.h>

// patches: [B=2, N=49, C=8, P=256, P=256] fp32; out: [B, C, 1024, 1024] fp32.
// Inverse-gather: output (h,w) covered by tiles {h>>7-1, h>>7}x{w>>7-1, w>>7}
// clamped to [0,6]. out = sum / (count + 1e-8).
//
// Each thread produces 4 float4 outputs at linear f4 indices
// idx + k*(TOTAL_F4/4), k=0..3. These share (h,w) and differ only in the
// bc-plane (bc, bc+4, bc+8, bc+12), so coverage/tile math is computed once
// and up to 16 independent float4 loads are in flight per thread.

namespace {
constexpr int NB = 2;
constexpr int NN = 49;
constexpr int NC = 8;
constexpr int PP = 256;
constexpr int HH = 1024;
constexpr int WW = 1024;
constexpr int TILES = 7;
constexpr int STRIDE = 128;

constexpr int TOTAL_F4   = NB * NC * HH * WW / 4;   // 4,194,304
constexpr int QUARTER_F4 = TOTAL_F4 / 4;            // 1,048,576 (= 4 bc-planes)
constexpr int CH_F4      = PP * PP / 4;             // 16,384 f4 per channel
constexpr int BATCH_F4   = NN * NC * CH_F4;         // f4 per batch in patches
constexpr int N_STRIDE_F4 = NC * CH_F4;             // f4 per tile index n
}

__global__ __launch_bounds__(256) void patch_merge_gather4(
    const float* __restrict__ patches, float* __restrict__ out)
{
    int idx = blockIdx.x * blockDim.x + threadIdx.x;   // f4 index, 0..QUARTER_F4-1
    if (idx >= QUARTER_F4) return;

    int w4 = idx & (WW / 4 - 1);    // 0..255
    int t  = idx >> 8;
    int h  = t & (HH - 1);          // 0..1023
    int bc0 = t >> 10;              // 0..3
    int w  = w4 << 2;

    // Covering tile ranges (boundaries at multiples of 128).
    int thh = h >> 7;
    int t0h = thh - 1 < 0 ? 0 : thh - 1;
    int t1h = thh > TILES - 1 ? TILES - 1 : thh;
    int tww = w >> 7;
    int t0w = tww - 1 < 0 ? 0 : tww - 1;
    int t1w = tww > TILES - 1 ? TILES - 1 : tww;

    // Plane offsets (in f4) for the 4 outputs: bc = bc0, bc0+4, bc0+8, bc0+12.
    // bc0 in 0..3: k=0 -> (b=0, c=bc0), k=1 -> (b=0, c=bc0+4),
    //              k=2 -> (b=1, c=bc0), k=3 -> (b=1, c=bc0+4).
    const int base0 = bc0 * CH_F4;
    int planeOff[4];
    planeOff[0] = base0;
    planeOff[1] = base0 + 4 * CH_F4;
    planeOff[2] = base0 + BATCH_F4;
    planeOff[3] = base0 + BATCH_F4 + 4 * CH_F4;

    float4 acc[4];
    #pragma unroll
    for (int k = 0; k < 4; ++k) acc[k] = make_float4(0.f, 0.f, 0.f, 0.f);
    int cnt = 0;

    const float4* __restrict__ p4 = reinterpret_cast<const float4*>(patches);

    #pragma unroll 2
    for (int th = t0h; th <= t1h; ++th) {
        int ph = h - th * STRIDE;          // 0..255
        #pragma unroll 2
        for (int tw = t0w; tw <= t1w; ++tw) {
            int pw = w - tw * STRIDE;      // 0..255, multiple of 4
            int n  = th * TILES + tw;
            int tileBase = n * N_STRIDE_F4 + ((ph * PP + pw) >> 2);
            ++cnt;
            #pragma unroll
            for (int k = 0; k < 4; ++k) {
                float4 v = __ldcs(p4 + planeOff[k] + tileBase);
                acc[k].x += v.x; acc[k].y += v.y;
                acc[k].z += v.z; acc[k].w += v.w;
            }
        }
    }

    float inv = 1.0f / ((float)cnt + 1e-8f);
    float4* __restrict__ o4 = reinterpret_cast<float4*>(out);
    #pragma unroll
    for (int k = 0; k < 4; ++k) {
        acc[k].x *= inv; acc[k].y *= inv; acc[k].z *= inv; acc[k].w *= inv;
        __stcs(o4 + idx + k * QUARTER_F4, acc[k]);
    }
}

extern "C" void kernel_launch(void* const* d_in, const int* in_sizes, int n_in,
                              void* d_out, int out_size)
{
    const float* patches = (const float*)d_in[0];
    float* out = (float*)d_out;
    dim3 block(256);
    dim3 grid((QUARTER_F4 + 255) / 256);   // 4096 blocks
    patch_merge_gather4<<<grid, block>>>(patches, out);
}

// round 7
// speedup vs baseline: 1.1471x; 1.0522x over previous
#include <cuda_runtime.h>
#include <cuda_bf16.h>

// patches: [B=2, N=49, C=8, P=256, P=256] fp32; out: [B, C, 1024, 1024] fp32.
// Inverse-gather: output (h,w) covered by tiles {h>>7-1, h>>7}x{w>>7-1, w>>7}
// clamped to [0,6]; count in {1,2,4}; out = sum / (count + 1e-8).
//
// Branch-free body: always load 4 candidate tiles (clamped indices; edge
// pixels load duplicate addresses, which hit L2) and accumulate with {0,1}
// weights. Every thread runs the same straight-line code -> 16 batched
// float4 loads, uniform work per warp. Persistent single-wave grid-stride.

namespace {
constexpr int NB = 2;
constexpr int NN = 49;
constexpr int NC = 8;
constexpr int PP = 256;
constexpr int HH = 1024;
constexpr int WW = 1024;
constexpr int TILES = 7;

constexpr int TOTAL_F4    = NB * NC * HH * WW / 4;  // 4,194,304
constexpr int QUARTER_F4  = TOTAL_F4 / 4;           // 1,048,576
constexpr int CH_F4       = PP * PP / 4;            // 16,384
constexpr int BATCH_F4    = NN * NC * CH_F4;
constexpr int N_STRIDE_F4 = NC * CH_F4;
}

__global__ __launch_bounds__(256) void patch_merge_gather4u(
    const float* __restrict__ patches, float* __restrict__ out)
{
    const float4* __restrict__ p4 = reinterpret_cast<const float4*>(patches);
    float4* __restrict__ o4 = reinterpret_cast<float4*>(out);

    const int stride = gridDim.x * blockDim.x;

    for (int idx = blockIdx.x * blockDim.x + threadIdx.x;
         idx < QUARTER_F4; idx += stride)
    {
        int w4  = idx & (WW / 4 - 1);   // 0..255
        int t   = idx >> 8;
        int h   = t & (HH - 1);         // 0..1023
        int bc0 = t >> 10;              // 0..3
        int w   = w4 << 2;

        int thh = h >> 7, tww = w >> 7;
        int th0 = thh - 1 < 0 ? 0 : thh - 1;
        int th1 = thh > TILES - 1 ? TILES - 1 : thh;
        int tw0 = tww - 1 < 0 ? 0 : tww - 1;
        int tw1 = tww > TILES - 1 ? TILES - 1 : tww;

        float wr = (th1 != th0) ? 1.f : 0.f;   // second row slot valid
        float wc = (tw1 != tw0) ? 1.f : 0.f;   // second col slot valid

        int ph0 = h - (th0 << 7), ph1 = h - (th1 << 7);
        int pw0 = w - (tw0 << 7), pw1 = w - (tw1 << 7);

        // 4 slot offsets within a channel plane (f4 units)
        int s00 = (th0 * TILES + tw0) * N_STRIDE_F4 + ((ph0 * PP + pw0) >> 2);
        int s01 = (th0 * TILES + tw1) * N_STRIDE_F4 + ((ph0 * PP + pw1) >> 2);
        int s10 = (th1 * TILES + tw0) * N_STRIDE_F4 + ((ph1 * PP + pw0) >> 2);
        int s11 = (th1 * TILES + tw1) * N_STRIDE_F4 + ((ph1 * PP + pw1) >> 2);

        // plane offsets for bc = bc0, bc0+4, bc0+8, bc0+12
        int base0 = bc0 * CH_F4;
        int plane[4];
        plane[0] = base0;
        plane[1] = base0 + 4 * CH_F4;
        plane[2] = base0 + BATCH_F4;
        plane[3] = base0 + BATCH_F4 + 4 * CH_F4;

        // 16 independent streaming loads, fully batched
        float4 v[16];
        #pragma unroll
        for (int k = 0; k < 4; ++k) {
            v[4 * k + 0] = __ldcs(p4 + plane[k] + s00);
            v[4 * k + 1] = __ldcs(p4 + plane[k] + s01);
            v[4 * k + 2] = __ldcs(p4 + plane[k] + s10);
            v[4 * k + 3] = __ldcs(p4 + plane[k] + s11);
        }

        float w01 = wc, w10 = wr, w11 = wr * wc;
        float cnt = (1.f + wr) * (1.f + wc);           // 1, 2, or 4 exactly
        float inv = 1.f / (cnt + 1e-8f);

        #pragma unroll
        for (int k = 0; k < 4; ++k) {
            float4 a;
            a.x = (v[4*k].x + w01 * v[4*k+1].x + w10 * v[4*k+2].x + w11 * v[4*k+3].x) * inv;
            a.y = (v[4*k].y + w01 * v[4*k+1].y + w10 * v[4*k+2].y + w11 * v[4*k+3].y) * inv;
            a.z = (v[4*k].z + w01 * v[4*k+1].z + w10 * v[4*k+2].z + w11 * v[4*k+3].z) * inv;
            a.w = (v[4*k].w + w01 * v[4*k+1].w + w10 * v[4*k+2].w + w11 * v[4*k+3].w) * inv;
            __stcs(o4 + idx + k * QUARTER_F4, a);
        }
    }
}

extern "C" void kernel_launch(void* const* d_in, const int* in_sizes, int n_in,
                              void* d_out, int out_size)
{
    const float* patches = (const float*)d_in[0];
    float* out = (float*)d_out;

    // Single balanced wave: grid = SMs * max resident CTAs (deterministic).
    int dev = 0, sms = 148, maxBlk = 0;
    cudaGetDevice(&dev);
    cudaDeviceGetAttribute(&sms, cudaDevAttrMultiProcessorCount, dev);
    cudaOccupancyMaxActiveBlocksPerMultiprocessor(
        &maxBlk, patch_merge_gather4u, 256, 0);
    if (maxBlk < 1) maxBlk = 2;
    int grid = sms * maxBlk;
    if (grid > (QUARTER_F4 + 255) / 256) grid = (QUARTER_F4 + 255) / 256;

    patch_merge_gather4u<<<grid, 256>>>(patches, out);
}